// round 14
// baseline (speedup 1.0000x reference)
#include <cuda_runtime.h>
#include <cfloat>

// Caffe-style RoI max pooling, bit-exact to the XLA-executed JAX reference.
//   x: [2,256,64,64] f32, rois: [2048,5] f32 -> out: [2048,256,7,7] f32
// Numerics: bin = roi_dim * RN(1/7) (0x3E124925) — XLA rewrites const-division
// into reciprocal multiply; rintf == jnp.round; __fmul_rn for boundary muls.
//
// Pipeline:
//   K1 (fused): read NCHW x through a shared slab, emit channels-last xt plus
//       all 8 max tables {1,2,4}^2 \ {1x1} (4x4 clamped neighborhood per point).
//   K2: pooling (round-12 structure, proven fastest): one block per roi,
//       one bin per warp, straight-line 2x2 end-clamped chunk max
//       (idempotent), sbin[49][SPITCH] staging, coalesced linear store.

#define PH 7
#define PW 7
#define SCALE 0.0625f
#define NTHR 256
#define SPITCH 258                 // floats per bin row; stride mod 32 == 2

#define HWSPAN 227                 // 32 outputs + 195 halo (3*64+3)
#define CPITCH 36                  // smem row pitch (floats): 16B-aligned, conflict-free

__device__ float g_xt [2 * 64 * 64 * 256];  // 1x1 (channels-last)
__device__ float g_p2 [2 * 64 * 64 * 256];  // 1 row x 2 cols
__device__ float g_p4 [2 * 64 * 64 * 256];  // 1 x 4
__device__ float g_c2 [2 * 64 * 64 * 256];  // 2 x 1
__device__ float g_c4 [2 * 64 * 64 * 256];  // 4 x 1
__device__ float g_r2 [2 * 64 * 64 * 256];  // 2 x 2
__device__ float g_h24[2 * 64 * 64 * 256];  // 2 rows x 4 cols
__device__ float g_h42[2 * 64 * 64 * 256];  // 4 rows x 2 cols
__device__ float g_r4 [2 * 64 * 64 * 256];  // 4 x 4

__device__ __forceinline__ float4 fmax4(float4 a, float4 b) {
    return make_float4(fmaxf(a.x, b.x), fmaxf(a.y, b.y),
                       fmaxf(a.z, b.z), fmaxf(a.w, b.w));
}

// ---- K1: fused transpose + table build ----
// Block: (hw-tile of 32, c-tile of 32, batch). 256 threads.
__global__ void __launch_bounds__(256)
fused_build_kernel(const float* __restrict__ x)
{
    __shared__ float sm[HWSPAN * CPITCH];   // 32.7 KB: [hw_rel][c]

    const int hw0 = blockIdx.x * 32;        // 128 tiles over HW=4096
    const int c0  = blockIdx.y * 32;        // 8 tiles over C=256
    const int b   = blockIdx.z;
    const int tid = threadIdx.x;
    const float* src = x + ((size_t)b * 256 + c0) * 4096;

    // Load slab: sm[rel][c] = x[b][c0+c][min(hw0+rel, 4095)], coalesced
    // (consecutive tid -> consecutive rel within one channel).
    for (int j = tid; j < HWSPAN * 32; j += 256) {
        const int c   = j / HWSPAN;
        const int rel = j - c * HWSPAN;
        const int hw  = min(hw0 + rel, 4095);
        sm[rel * CPITCH + c] = src[(size_t)c * 4096 + hw];
    }
    __syncthreads();

    // Compute: thread -> (hw_rel = tid>>3, c4 = (tid&7)*4).
    const int hw_rel = tid >> 3;
    const int c4f    = (tid & 7) * 4;
    const int hw = hw0 + hw_rel;
    const int h = hw >> 6;
    const int w = hw & 63;

    float4 v[4][4];
    #pragma unroll
    for (int i = 0; i < 4; ++i) {
        const int hh = min(h + i, 63);
        #pragma unroll
        for (int j = 0; j < 4; ++j) {
            const int ww = min(w + j, 63);
            const int rel = hh * 64 + ww - hw0;   // in [hw_rel, 226]
            v[i][j] = *(const float4*)(sm + rel * CPITCH + c4f);
        }
    }

    float4 p2r[4], p4r[4];
    #pragma unroll
    for (int i = 0; i < 4; ++i) {
        p2r[i] = fmax4(v[i][0], v[i][1]);
        p4r[i] = fmax4(p2r[i], fmax4(v[i][2], v[i][3]));
    }
    const float4 c2  = fmax4(v[0][0], v[1][0]);
    const float4 c4v = fmax4(c2, fmax4(v[2][0], v[3][0]));
    const float4 r2  = fmax4(p2r[0], p2r[1]);
    const float4 h42 = fmax4(r2, fmax4(p2r[2], p2r[3]));
    const float4 h24 = fmax4(p4r[0], p4r[1]);
    const float4 r4  = fmax4(h24, fmax4(p4r[2], p4r[3]));

    const size_t o = (size_t)b * 4096 * 256 + (size_t)hw * 256 + c0 + c4f;
    *(float4*)(g_xt  + o) = v[0][0];
    *(float4*)(g_p2  + o) = p2r[0];
    *(float4*)(g_p4  + o) = p4r[0];
    *(float4*)(g_c2  + o) = c2;
    *(float4*)(g_c4  + o) = c4v;
    *(float4*)(g_r2  + o) = r2;
    *(float4*)(g_h24 + o) = h24;
    *(float4*)(g_h42 + o) = h42;
    *(float4*)(g_r4  + o) = r4;
}

// ---- K2: pooling, one block per roi (round-12 structure) ----
__global__ void __launch_bounds__(NTHR, 4)
roipool_cl_kernel(const float* __restrict__ rois,
                  float* __restrict__ out)
{
    __shared__ float sbin[49 * SPITCH];       // 50.6 KB: [bin][channel]
    __shared__ const float* s_tbl[49];
    __shared__ int s_h0[49], s_h1[49], s_w0[49], s_w1[49], s_emp[49];

    const int H = 64, W = 64;
    const int r = blockIdx.x;
    const float* roi = rois + (size_t)r * 5;

    // Setup: threads 0..48 compute their bin's chunk descriptor.
    {
        const int t = threadIdx.x;
        if (t < 49) {
            const int xs = (int)rintf(__fmul_rn(roi[1], SCALE));
            const int ys = (int)rintf(__fmul_rn(roi[2], SCALE));
            const int xe = (int)rintf(__fmul_rn(roi[3], SCALE));
            const int ye = (int)rintf(__fmul_rn(roi[4], SCALE));
            const float roi_w = (float)max(xe - xs + 1, 1);
            const float roi_h = (float)max(ye - ys + 1, 1);
            const float rc7 = __uint_as_float(0x3E124925u);   // RN(1/7)
            const float bw = __fmul_rn(roi_w, rc7);
            const float bh = __fmul_rn(roi_h, rc7);
            const float fph = (float)(t / 7);
            const float fpw = (float)(t % 7);
            const int ws = min(max((int)floorf(__fmul_rn(fpw, bw)) + xs, 0), W);
            const int we = min(max((int)ceilf(__fmul_rn(fpw + 1.0f, bw)) + xs, 0), W);
            const int hs = min(max((int)floorf(__fmul_rn(fph, bh)) + ys, 0), H);
            const int he = min(max((int)ceilf(__fmul_rn(fph + 1.0f, bh)) + ys, 0), H);
            const int nh = he - hs, nw = we - ws;
            const int empty = (nh <= 0) | (nw <= 0);
            const int sh = (nh >= 4) ? 4 : ((nh >= 2) ? 2 : 1);
            const int sw = (nw >= 4) ? 4 : ((nw >= 2) ? 2 : 1);
            const int ih = (nh >= 4) ? 2 : ((nh >= 2) ? 1 : 0);
            const int iw = (nw >= 4) ? 2 : ((nw >= 2) ? 1 : 0);
            const float* tb;
            switch (ih * 3 + iw) {
                case 0: tb = g_xt;  break;
                case 1: tb = g_p2;  break;
                case 2: tb = g_p4;  break;
                case 3: tb = g_c2;  break;
                case 4: tb = g_r2;  break;
                case 5: tb = g_h24; break;
                case 6: tb = g_c4;  break;
                case 7: tb = g_h42; break;
                default: tb = g_r4; break;
            }
            s_tbl[t] = tb + (size_t)((int)roi[0]) * 4096 * 256;
            s_h0[t] = empty ? 0 : hs;
            s_h1[t] = empty ? 0 : (he - sh);
            s_w0[t] = empty ? 0 : ws;
            s_w1[t] = empty ? 0 : (we - sw);
            s_emp[t] = empty;
        }
    }
    __syncthreads();

    const int wid  = threadIdx.x >> 5;      // 8 warps
    const int lane = threadIdx.x & 31;

    // Phase 1: straight-line 2x2 chunk max per bin (idempotent overlap).
    for (int bin = wid; bin < 49; bin += 8) {
        const float* tb = s_tbl[bin] + 4 * lane;
        const int h0 = s_h0[bin], h1 = s_h1[bin];
        const int w0 = s_w0[bin], w1 = s_w1[bin];

        const float* p00 = tb + ((size_t)(h0 * 64 + w0)) * 256;
        const float* p01 = tb + ((size_t)(h0 * 64 + w1)) * 256;
        const float* p10 = tb + ((size_t)(h1 * 64 + w0)) * 256;
        const float* p11 = tb + ((size_t)(h1 * 64 + w1)) * 256;

        const float4 a00 = *(const float4*)p00;
        const float4 a01 = *(const float4*)p01;
        const float4 a10 = *(const float4*)p10;
        const float4 a11 = *(const float4*)p11;
        const float4 b00 = *(const float4*)(p00 + 128);
        const float4 b01 = *(const float4*)(p01 + 128);
        const float4 b10 = *(const float4*)(p10 + 128);
        const float4 b11 = *(const float4*)(p11 + 128);

        float4 m0 = fmax4(fmax4(a00, a01), fmax4(a10, a11));
        float4 m1 = fmax4(fmax4(b00, b01), fmax4(b10, b11));
        if (s_emp[bin]) {
            m0 = make_float4(0.0f, 0.0f, 0.0f, 0.0f);
            m1 = m0;
        }

        float* s = sbin + bin * SPITCH + 4 * lane;
        *(float2*)(s)       = make_float2(m0.x, m0.y);
        *(float2*)(s + 2)   = make_float2(m0.z, m0.w);
        *(float2*)(s + 128) = make_float2(m1.x, m1.y);
        *(float2*)(s + 130) = make_float2(m1.z, m1.w);
    }
    __syncthreads();

    // Phase 2: coalesced linear store; (c,bin) maintained incrementally.
    float* out_r = out + (size_t)r * 12544;
    {
        int i = threadIdx.x;
        int c = i / 49;
        int bin = i - c * 49;
        #pragma unroll 1
        for (int k = 0; k < 49; ++k) {
            out_r[i] = sbin[bin * SPITCH + c];
            i += NTHR;
            c += 5; bin += 11;
            if (bin >= 49) { bin -= 49; ++c; }
        }
    }
}

extern "C" void kernel_launch(void* const* d_in, const int* in_sizes, int n_in,
                              void* d_out, int out_size)
{
    const float* x    = (const float*)d_in[0];
    const float* rois = (const float*)d_in[1];
    float* out        = (float*)d_out;
    const int R = in_sizes[1] / 5;

    dim3 bg(128, 8, 2);
    fused_build_kernel<<<bg, 256>>>(x);
    roipool_cl_kernel<<<R, NTHR>>>(rois, out);
}

// round 15
// speedup vs baseline: 1.2754x; 1.2754x over previous
#include <cuda_runtime.h>
#include <cfloat>

// Caffe-style RoI max pooling, bit-exact to the XLA-executed JAX reference.
//   x: [2,256,64,64] f32, rois: [2048,5] f32 -> out: [2048,256,7,7] f32
// Numerics: bin = roi_dim * RN(1/7) (0x3E124925) — XLA rewrites const-division
// into reciprocal multiply; rintf == jnp.round; __fmul_rn for boundary muls.
//
// Pipeline (round-12 prep, proven fastest):
//   K1: transpose x -> xt[b][h][w][c] (channels-last).
//   K2: fused table build: all 8 max tables {1,2,4}^2 \ {1x1} from a 4x4
//       xt neighborhood in registers.
//   K3: pooling. Steps {1,2,4} -> every bin window (<=7/dim) is at most
//       2x2 end-clamped chunks (idempotent max). Phase 1 now branches on a
//       warp-uniform chunk-multiplicity case (1x1 / 1x2 / 2x1 / 2x2) and
//       issues only the needed 2/4/4/8 LDG.128 (no duplicate loads).

#define PH 7
#define PW 7
#define SCALE 0.0625f
#define NTHR 256
#define SPITCH 258                 // floats per bin row; stride mod 32 == 2

__device__ float g_xt [2 * 64 * 64 * 256];  // 1x1
__device__ float g_p2 [2 * 64 * 64 * 256];  // 1 row x 2 cols
__device__ float g_p4 [2 * 64 * 64 * 256];  // 1 x 4
__device__ float g_c2 [2 * 64 * 64 * 256];  // 2 x 1
__device__ float g_c4 [2 * 64 * 64 * 256];  // 4 x 1
__device__ float g_r2 [2 * 64 * 64 * 256];  // 2 x 2
__device__ float g_h24[2 * 64 * 64 * 256];  // 2 rows x 4 cols
__device__ float g_h42[2 * 64 * 64 * 256];  // 4 rows x 2 cols
__device__ float g_r4 [2 * 64 * 64 * 256];  // 4 x 4

__device__ __forceinline__ float4 fmax4(float4 a, float4 b) {
    return make_float4(fmaxf(a.x, b.x), fmaxf(a.y, b.y),
                       fmaxf(a.z, b.z), fmaxf(a.w, b.w));
}

// ---- K1: [b][c][hw] -> [b][hw][c] tiled transpose ----
__global__ void __launch_bounds__(256)
transpose_kernel(const float* __restrict__ x)
{
    __shared__ float t[32][33];
    const int tx = threadIdx.x & 31;
    const int ty = threadIdx.x >> 5;
    const int hw0 = blockIdx.x * 32;
    const int c0  = blockIdx.y * 32;
    const int b   = blockIdx.z;
    const float* src = x + (size_t)b * 256 * 4096;
    float* dst = g_xt + (size_t)b * 4096 * 256;

    #pragma unroll
    for (int i = 0; i < 32; i += 8)
        t[ty + i][tx] = src[(size_t)(c0 + ty + i) * 4096 + hw0 + tx];
    __syncthreads();
    #pragma unroll
    for (int i = 0; i < 32; i += 8)
        dst[(size_t)(hw0 + ty + i) * 256 + c0 + tx] = t[tx][ty + i];
}

// ---- K2: fused table build ----
__global__ void __launch_bounds__(256)
build_tables_kernel()
{
    const int idx = blockIdx.x * 256 + threadIdx.x;   // (b,h,w,c4)
    const int c4 = (idx & 63) * 4;
    const int w  = (idx >> 6) & 63;
    const int h  = (idx >> 12) & 63;
    const int b  = idx >> 18;
    const size_t bp = (size_t)b * 4096 * 256;

    const int w1 = min(w + 1, 63), w2 = min(w + 2, 63), w3 = min(w + 3, 63);

    float4 p2r[4], p4r[4], col0[4];
    #pragma unroll
    for (int i = 0; i < 4; ++i) {
        const int hh = min(h + i, 63);
        const float* row = g_xt + bp + ((size_t)(hh * 64)) * 256 + c4;
        const float4 a0 = *(const float4*)(row + (size_t)w  * 256);
        const float4 a1 = *(const float4*)(row + (size_t)w1 * 256);
        const float4 a2 = *(const float4*)(row + (size_t)w2 * 256);
        const float4 a3 = *(const float4*)(row + (size_t)w3 * 256);
        col0[i] = a0;
        p2r[i] = fmax4(a0, a1);
        p4r[i] = fmax4(p2r[i], fmax4(a2, a3));
    }

    const float4 c2  = fmax4(col0[0], col0[1]);
    const float4 c4v = fmax4(c2, fmax4(col0[2], col0[3]));
    const float4 r2  = fmax4(p2r[0], p2r[1]);
    const float4 h42 = fmax4(r2, fmax4(p2r[2], p2r[3]));
    const float4 h24 = fmax4(p4r[0], p4r[1]);
    const float4 r4  = fmax4(h24, fmax4(p4r[2], p4r[3]));

    const size_t o = bp + ((size_t)(h * 64 + w)) * 256 + c4;
    *(float4*)(g_p2  + o) = p2r[0];
    *(float4*)(g_p4  + o) = p4r[0];
    *(float4*)(g_c2  + o) = c2;
    *(float4*)(g_c4  + o) = c4v;
    *(float4*)(g_r2  + o) = r2;
    *(float4*)(g_h24 + o) = h24;
    *(float4*)(g_h42 + o) = h42;
    *(float4*)(g_r4  + o) = r4;
}

// ---- K3: pooling, one block per roi ----
__global__ void __launch_bounds__(NTHR, 4)
roipool_cl_kernel(const float* __restrict__ rois,
                  float* __restrict__ out)
{
    __shared__ float sbin[49 * SPITCH];       // 50.6 KB: [bin][channel]
    __shared__ const float* s_tbl[49];
    __shared__ int s_h0[49], s_h1[49], s_w0[49], s_w1[49], s_case[49];

    const int H = 64, W = 64;
    const int r = blockIdx.x;
    const float* roi = rois + (size_t)r * 5;

    // Setup: threads 0..48 compute their bin's chunk descriptor.
    {
        const int t = threadIdx.x;
        if (t < 49) {
            const int xs = (int)rintf(__fmul_rn(roi[1], SCALE));
            const int ys = (int)rintf(__fmul_rn(roi[2], SCALE));
            const int xe = (int)rintf(__fmul_rn(roi[3], SCALE));
            const int ye = (int)rintf(__fmul_rn(roi[4], SCALE));
            const float roi_w = (float)max(xe - xs + 1, 1);
            const float roi_h = (float)max(ye - ys + 1, 1);
            const float rc7 = __uint_as_float(0x3E124925u);   // RN(1/7)
            const float bw = __fmul_rn(roi_w, rc7);
            const float bh = __fmul_rn(roi_h, rc7);
            const float fph = (float)(t / 7);
            const float fpw = (float)(t % 7);
            const int ws = min(max((int)floorf(__fmul_rn(fpw, bw)) + xs, 0), W);
            const int we = min(max((int)ceilf(__fmul_rn(fpw + 1.0f, bw)) + xs, 0), W);
            const int hs = min(max((int)floorf(__fmul_rn(fph, bh)) + ys, 0), H);
            const int he = min(max((int)ceilf(__fmul_rn(fph + 1.0f, bh)) + ys, 0), H);
            const int nh = he - hs, nw = we - ws;
            const int empty = (nh <= 0) | (nw <= 0);
            const int sh = (nh >= 4) ? 4 : ((nh >= 2) ? 2 : 1);
            const int sw = (nw >= 4) ? 4 : ((nw >= 2) ? 2 : 1);
            const int ih = (nh >= 4) ? 2 : ((nh >= 2) ? 1 : 0);
            const int iw = (nw >= 4) ? 2 : ((nw >= 2) ? 1 : 0);
            const float* tb;
            switch (ih * 3 + iw) {
                case 0: tb = g_xt;  break;
                case 1: tb = g_p2;  break;
                case 2: tb = g_p4;  break;
                case 3: tb = g_c2;  break;
                case 4: tb = g_r2;  break;
                case 5: tb = g_h24; break;
                case 6: tb = g_c4;  break;
                case 7: tb = g_h42; break;
                default: tb = g_r4; break;
            }
            const int h0 = empty ? 0 : hs;
            const int h1 = empty ? 0 : (he - sh);
            const int w0 = empty ? 0 : ws;
            const int w1 = empty ? 0 : (we - sw);
            s_tbl[t] = tb + (size_t)((int)roi[0]) * 4096 * 256;
            s_h0[t] = h0; s_h1[t] = h1;
            s_w0[t] = w0; s_w1[t] = w1;
            // case: 4 = empty; else dh*2+dw (chunk multiplicity per dim)
            s_case[t] = empty ? 4 : (((h1 > h0) ? 2 : 0) | ((w1 > w0) ? 1 : 0));
        }
    }
    __syncthreads();

    const int wid  = threadIdx.x >> 5;      // 8 warps
    const int lane = threadIdx.x & 31;

    // Phase 1: warp-uniform case switch; issue only the needed LDG.128s.
    for (int bin = wid; bin < 49; bin += 8) {
        const float* tb = s_tbl[bin] + 4 * lane;
        const int h0 = s_h0[bin], h1 = s_h1[bin];
        const int w0 = s_w0[bin], w1 = s_w1[bin];
        const int cs = s_case[bin];

        const float* p00 = tb + ((size_t)(h0 * 64 + w0)) * 256;
        float4 m0, m1;

        switch (cs) {
        case 0: {                           // single chunk
            m0 = *(const float4*)p00;
            m1 = *(const float4*)(p00 + 128);
        } break;
        case 1: {                           // two chunks along w
            const float* p01 = tb + ((size_t)(h0 * 64 + w1)) * 256;
            const float4 a00 = *(const float4*)p00;
            const float4 a01 = *(const float4*)p01;
            const float4 b00 = *(const float4*)(p00 + 128);
            const float4 b01 = *(const float4*)(p01 + 128);
            m0 = fmax4(a00, a01);
            m1 = fmax4(b00, b01);
        } break;
        case 2: {                           // two chunks along h
            const float* p10 = tb + ((size_t)(h1 * 64 + w0)) * 256;
            const float4 a00 = *(const float4*)p00;
            const float4 a10 = *(const float4*)p10;
            const float4 b00 = *(const float4*)(p00 + 128);
            const float4 b10 = *(const float4*)(p10 + 128);
            m0 = fmax4(a00, a10);
            m1 = fmax4(b00, b10);
        } break;
        case 3: {                           // 2x2 chunks
            const float* p01 = tb + ((size_t)(h0 * 64 + w1)) * 256;
            const float* p10 = tb + ((size_t)(h1 * 64 + w0)) * 256;
            const float* p11 = tb + ((size_t)(h1 * 64 + w1)) * 256;
            const float4 a00 = *(const float4*)p00;
            const float4 a01 = *(const float4*)p01;
            const float4 a10 = *(const float4*)p10;
            const float4 a11 = *(const float4*)p11;
            const float4 b00 = *(const float4*)(p00 + 128);
            const float4 b01 = *(const float4*)(p01 + 128);
            const float4 b10 = *(const float4*)(p10 + 128);
            const float4 b11 = *(const float4*)(p11 + 128);
            m0 = fmax4(fmax4(a00, a01), fmax4(a10, a11));
            m1 = fmax4(fmax4(b00, b01), fmax4(b10, b11));
        } break;
        default: {                          // empty bin
            m0 = make_float4(0.0f, 0.0f, 0.0f, 0.0f);
            m1 = m0;
        } break;
        }

        float* s = sbin + bin * SPITCH + 4 * lane;
        *(float2*)(s)       = make_float2(m0.x, m0.y);
        *(float2*)(s + 2)   = make_float2(m0.z, m0.w);
        *(float2*)(s + 128) = make_float2(m1.x, m1.y);
        *(float2*)(s + 130) = make_float2(m1.z, m1.w);
    }
    __syncthreads();

    // Phase 2: coalesced linear store; (c,bin) maintained incrementally.
    float* out_r = out + (size_t)r * 12544;
    {
        int i = threadIdx.x;
        int c = i / 49;
        int bin = i - c * 49;
        #pragma unroll 1
        for (int k = 0; k < 49; ++k) {
            out_r[i] = sbin[bin * SPITCH + c];
            i += NTHR;
            c += 5; bin += 11;
            if (bin >= 49) { bin -= 49; ++c; }
        }
    }
}

extern "C" void kernel_launch(void* const* d_in, const int* in_sizes, int n_in,
                              void* d_out, int out_size)
{
    const float* x    = (const float*)d_in[0];
    const float* rois = (const float*)d_in[1];
    float* out        = (float*)d_out;
    const int R = in_sizes[1] / 5;

    dim3 tg(128, 8, 2);
    transpose_kernel<<<tg, 256>>>(x);
    build_tables_kernel<<<2048, 256>>>();
    roipool_cl_kernel<<<R, NTHR>>>(rois, out);
}